// round 11
// baseline (speedup 1.0000x reference)
#include <cuda_runtime.h>
#include <cuda_bf16.h>
#include <math.h>

// Problem constants
#define Bv 4
#define Nv 256
#define Dv 128
#define Hv 256
#define Kv 8
#define Cv 12
#define ROWS (Bv * Nv)      // 1024

// Global scratch
__device__ uint2 WPK_buf[Dv * (Hv / 2)];                 // packed gate W_mid/W_bot bf16 pairs
__device__ __nv_bfloat16 s_img[ROWS * 136];              // bf16 s rows, 272B stride
__device__ float g_scores[ROWS * Nv];
__device__ float ub_g[ROWS * Hv];                        // Ug + bg1
__device__ float uab_g[ROWS * Hv];                       // Ua + ba1

// ---------------------------------------------------------------------------
// f32x2 helpers
// ---------------------------------------------------------------------------
__device__ __forceinline__ void ffma2(unsigned long long& d,
                                      unsigned long long a,
                                      unsigned long long b) {
    asm("fma.rn.f32x2 %0, %1, %2, %0;" : "+l"(d) : "l"(a), "l"(b));
}
__device__ __forceinline__ unsigned long long pack2(float x, float y) {
    unsigned long long r;
    asm("mov.b64 %0, {%1, %2};" : "=l"(r) : "f"(x), "f"(y));
    return r;
}
__device__ __forceinline__ float2 unpack2(unsigned long long v) {
    float2 r;
    asm("mov.b64 {%0, %1}, %2;" : "=f"(r.x), "=f"(r.y) : "l"(v));
    return r;
}

// ---------------------------------------------------------------------------
// MMA helpers
// ---------------------------------------------------------------------------
__device__ __forceinline__ void ldsm4(unsigned* r, unsigned addr) {
    asm volatile("ldmatrix.sync.aligned.m8n8.x4.shared.b16 {%0,%1,%2,%3}, [%4];"
                 : "=r"(r[0]), "=r"(r[1]), "=r"(r[2]), "=r"(r[3]) : "r"(addr));
}
__device__ __forceinline__ void ldsm4t(unsigned* r, unsigned addr) {
    asm volatile("ldmatrix.sync.aligned.m8n8.x4.trans.shared.b16 {%0,%1,%2,%3}, [%4];"
                 : "=r"(r[0]), "=r"(r[1]), "=r"(r[2]), "=r"(r[3]) : "r"(addr));
}
__device__ __forceinline__ void mma16816(float* d, const unsigned* a, unsigned b0, unsigned b1) {
    asm volatile("mma.sync.aligned.m16n8k16.row.col.f32.bf16.bf16.f32 "
                 "{%0,%1,%2,%3}, {%4,%5,%6,%7}, {%8,%9}, {%0,%1,%2,%3};"
                 : "+f"(d[0]), "+f"(d[1]), "+f"(d[2]), "+f"(d[3])
                 : "r"(a[0]), "r"(a[1]), "r"(a[2]), "r"(a[3]), "r"(b0), "r"(b1));
}

// ---------------------------------------------------------------------------
// prep: pack WPK + s -> bf16 image
// ---------------------------------------------------------------------------
__global__ __launch_bounds__(256) void prep_kernel(const float* __restrict__ s,
                                                   const float* __restrict__ Wg1)
{
    int bi0 = blockIdx.x * 2;
    int tid = threadIdx.x;
    // s rows -> image
    {
        int r = tid >> 7, d = tid & 127;
        s_img[(bi0 + r) * 136 + d] = __float2bfloat16(s[(bi0 + r) * Dv + d]);
    }
    // WPK: 32 entries per block
    if (tid < 32) {
        int idx = blockIdx.x * 32 + tid;
        int d  = idx >> 7;
        int hp = idx & 127;
        int h0 = hp * 2;
        float m0 = Wg1[(Dv + d) * Hv + h0];
        float m1 = Wg1[(Dv + d) * Hv + h0 + 1];
        float b0 = Wg1[(2 * Dv + d) * Hv + h0];
        float b1 = Wg1[(2 * Dv + d) * Hv + h0 + 1];
        __nv_bfloat162 mp = __floats2bfloat162_rn(m0, m1);
        __nv_bfloat162 bp = __floats2bfloat162_rn(b0, b1);
        uint2 v;
        v.x = *(unsigned*)&mp;
        v.y = *(unsigned*)&bp;
        WPK_buf[idx] = v;
    }
}

// ---------------------------------------------------------------------------
// gscore: 1024 blocks = 512 i-pairs x 2 j-halves. M=128 tile, 3 blocks/SM.
// ---------------------------------------------------------------------------
#define CH 72
#define AOFS   0        // 34816 : A [128 j][136 d] bf16 (272B rows)
#define COFS   34816    // 2 x 18432 c bufs ([128 d][CH] bf16)
#define UBOFS  71680    // 2 x 256 f32 (Ug + bg1)
#define W2OFS  73728    // 256 f32
#define SIOFS  74752    // 2 x 128 f32
#define SIBOFS 75776    // 2 x 128 uint (bf16x2 dup)
#define GS_SMEM 76800

__global__ __launch_bounds__(256, 3) void gscore_kernel(
    const float* __restrict__ s,
    const float* __restrict__ Wg1,
    const float* __restrict__ bg1,
    const float* __restrict__ Wg2,
    const float* __restrict__ Wa1,
    const float* __restrict__ ba1)
{
    extern __shared__ unsigned char dynsm[];
    float* ub_sm   = (float*)(dynsm + UBOFS);
    float* w2_sm   = (float*)(dynsm + W2OFS);
    float* si_sm   = (float*)(dynsm + SIOFS);
    unsigned* sib  = (unsigned*)(dynsm + SIBOFS);
    float* part_sm = (float*)(dynsm + COFS);       // alias post-GEMM [4][128]

    int blk = blockIdx.x;
    int jt  = blk & 1;
    int bi0 = (blk >> 1) * 2;
    int b   = bi0 >> 8;
    int tid = threadIdx.x;
    int lane = tid & 31;
    int warp = tid >> 5;

    // A copy: 128 image rows x 272B = 2176 uint4
    {
        const uint4* src = (const uint4*)((const unsigned char*)s_img
                                          + (size_t)(b * 256 + jt * 128) * 272);
        uint4* dst = (uint4*)(dynsm + AOFS);
#pragma unroll
        for (int k = 0; k < 9; k++) {
            int t = k * 256 + tid;
            if (t < 2176) dst[t] = src[t];
        }
    }
    // si
    {
        int r = tid >> 7, d = tid & 127;
        si_sm[r * 128 + d] = s[(bi0 + r) * Dv + d];
    }
    w2_sm[tid] = Wg2[tid];
    __syncthreads();

    // sib (bf16 dup pairs)
    {
        int r = tid >> 7, d = tid & 127;
        __nv_bfloat16 bv = __float2bfloat16(si_sm[r * 128 + d]);
        __nv_bfloat162 bb = __nv_bfloat162(bv, bv);
        sib[r * 128 + d] = *(unsigned*)&bb;
    }

    // U (gate both rows; att rows only for jt==0, stored for topk)
    {
        int h = tid;
        float ug0 = bg1[h], ug1 = ug0;
        float ua0 = 0.f, ua1 = 0.f;
        if (jt == 0) { ua0 = ba1[h]; ua1 = ua0; }
#pragma unroll 8
        for (int d = 0; d < Dv; d++) {
            float wg = Wg1[d * Hv + h];
            float s0 = si_sm[d];
            float s1 = si_sm[128 + d];
            ug0 = fmaf(s0, wg, ug0);
            ug1 = fmaf(s1, wg, ug1);
            if (jt == 0) {
                float wa = Wa1[d * Hv + h];
                ua0 = fmaf(s0, wa, ua0);
                ua1 = fmaf(s1, wa, ua1);
            }
        }
        ub_sm[h]       = ug0;
        ub_sm[256 + h] = ug1;
        if (jt == 0) {
            ub_g[bi0 * Hv + h]        = ug0;
            ub_g[(bi0 + 1) * Hv + h]  = ug1;
            uab_g[bi0 * Hv + h]       = ua0;
            uab_g[(bi0 + 1) * Hv + h] = ua1;
        }
    }
    __syncthreads();

    // build c buf 0 (ii=0, hc=0)
    {
        unsigned char* cbuf = dynsm + COFS;
        int bld_d = tid >> 5, bld_hp = tid & 31;
#pragma unroll
        for (int k = 0; k < 16; k++) {
            int dd = k * 8 + bld_d;
            uint2 wv = WPK_buf[dd * 128 + bld_hp];
            __nv_bfloat162 sp = *(__nv_bfloat162*)&sib[dd];
            __nv_bfloat162 mp = *(__nv_bfloat162*)&wv.x;
            __nv_bfloat162 bp = *(__nv_bfloat162*)&wv.y;
            __nv_bfloat162 c = __hfma2(sp, bp, mp);
            *(unsigned*)(cbuf + dd * 144 + bld_hp * 4) = *(unsigned*)&c;
        }
    }
    __syncthreads();

    const unsigned sbase  = (unsigned)__cvta_generic_to_shared(dynsm + AOFS);
    const unsigned cbase0 = (unsigned)__cvta_generic_to_shared(dynsm + COFS);
    int wm_ = (warp & 3) * 32;
    int wn  = (warp >> 2) * 32;
    int aRow  = wm_ + (lane & 15);
    int aColB = (lane >> 4) * 16;
    int bK    = lane & 15;
    int bH    = wn + ((lane >> 4) << 3);
    int bld_d = tid >> 5, bld_hp = tid & 31;

    float sreg[2][2][2];
#pragma unroll
    for (int ii = 0; ii < 2; ii++)
#pragma unroll
        for (int mt = 0; mt < 2; mt++) { sreg[ii][mt][0] = 0.f; sreg[ii][mt][1] = 0.f; }

#pragma unroll 1
    for (int r = 0; r < 8; r++) {
        int hc = r >> 1, ii = r & 1;
        int nxt = r + 1;

        float acc[8][4];
#pragma unroll
        for (int q = 0; q < 8; q++) { acc[q][0]=0.f; acc[q][1]=0.f; acc[q][2]=0.f; acc[q][3]=0.f; }

        unsigned cb = cbase0 + (unsigned)((r & 1) * 18432);
#pragma unroll
        for (int ks = 0; ks < 8; ks++) {
            unsigned a[2][4], bq[2][4];
#pragma unroll
            for (int mt = 0; mt < 2; mt++) {
                unsigned addr = sbase + (unsigned)((aRow + mt * 16) * 272 + ks * 32) + aColB;
                ldsm4(a[mt], addr);
            }
#pragma unroll
            for (int nt = 0; nt < 2; nt++) {
                unsigned addr = cb + (unsigned)((ks * 16 + bK) * 144 + (bH + nt * 16) * 2);
                ldsm4t(bq[nt], addr);
            }
#pragma unroll
            for (int mt = 0; mt < 2; mt++)
#pragma unroll
                for (int n8 = 0; n8 < 4; n8++)
                    mma16816(acc[mt * 4 + n8], a[mt],
                             bq[n8 >> 1][(n8 & 1) * 2], bq[n8 >> 1][(n8 & 1) * 2 + 1]);
        }

        // build next c buf (inline WPK loads; latency hidden by other warps' MMA)
        if (nxt < 8) {
            int iiN = nxt & 1, hcN = nxt >> 1;
            unsigned char* cbuf = dynsm + COFS + (nxt & 1) * 18432;
#pragma unroll
            for (int k = 0; k < 16; k++) {
                int dd = k * 8 + bld_d;
                uint2 wv = WPK_buf[dd * 128 + hcN * 32 + bld_hp];
                __nv_bfloat162 sp = *(__nv_bfloat162*)&sib[iiN * 128 + dd];
                __nv_bfloat162 mp = *(__nv_bfloat162*)&wv.x;
                __nv_bfloat162 bp = *(__nv_bfloat162*)&wv.y;
                __nv_bfloat162 c = __hfma2(sp, bp, mp);
                *(unsigned*)(cbuf + dd * 144 + bld_hp * 4) = *(unsigned*)&c;
            }
        }

        // epilogue into register partials
        {
            int hb = hc * 64 + wn + (lane & 3) * 2;
            const float2* u2p = (const float2*)(ub_sm + ii * 256);
            const float2* w2p = (const float2*)w2_sm;
            float2 uu[4], ww[4];
#pragma unroll
            for (int n8 = 0; n8 < 4; n8++) {
                uu[n8] = u2p[(hb + n8 * 8) >> 1];
                ww[n8] = w2p[(hb + n8 * 8) >> 1];
            }
#pragma unroll
            for (int mt = 0; mt < 2; mt++) {
                float p0 = sreg[ii][mt][0];
                float p1 = sreg[ii][mt][1];
#pragma unroll
                for (int n8 = 0; n8 < 4; n8++) {
                    const float* A = acc[mt * 4 + n8];
                    p0 = fmaf(fmaxf(A[0] + uu[n8].x, 0.f), ww[n8].x, p0);
                    p0 = fmaf(fmaxf(A[1] + uu[n8].y, 0.f), ww[n8].y, p0);
                    p1 = fmaf(fmaxf(A[2] + uu[n8].x, 0.f), ww[n8].x, p1);
                    p1 = fmaf(fmaxf(A[3] + uu[n8].y, 0.f), ww[n8].y, p1);
                }
                sreg[ii][mt][0] = p0;
                sreg[ii][mt][1] = p1;
            }
        }
        __syncthreads();
    }

    // final reduce: quad shfl then 2 n-warp parts in smem
    {
        int nw = warp >> 2;
#pragma unroll
        for (int ii = 0; ii < 2; ii++)
#pragma unroll
            for (int mt = 0; mt < 2; mt++)
#pragma unroll
                for (int half = 0; half < 2; half++) {
                    float v = sreg[ii][mt][half];
                    v += __shfl_xor_sync(0xffffffffu, v, 1);
                    v += __shfl_xor_sync(0xffffffffu, v, 2);
                    if ((lane & 3) == 0) {
                        int j = wm_ + mt * 16 + (lane >> 2) + half * 8;
                        part_sm[(ii * 2 + nw) * 128 + j] = v;
                    }
                }
    }
    __syncthreads();
    {
        int ii = tid >> 7, jl = tid & 127;
        float v = part_sm[(ii * 2) * 128 + jl] + part_sm[(ii * 2 + 1) * 128 + jl];
        g_scores[(bi0 + ii) * Nv + jt * 128 + jl] = v;
    }
}

// ---------------------------------------------------------------------------
// topk: 512 blocks (2 rows). top-12, exact gate rescore, top-8, att for 8.
// ---------------------------------------------------------------------------
__global__ __launch_bounds__(256) void topk_kernel(
    const float* __restrict__ s,
    const float* __restrict__ Wg1,
    const float* __restrict__ Wg2,
    const float* __restrict__ bg2,
    const float* __restrict__ Wa1,
    const float* __restrict__ Wa2,
    const float* __restrict__ ba2,
    float* __restrict__ ctx,
    float* __restrict__ gate,
    float* __restrict__ att)
{
    __shared__ float sc[2][Nv];
    __shared__ __align__(16) float selT[Dv][24];
    __shared__ __align__(16) float selA[Dv][16];
    __shared__ float si2[2][Dv];
    __shared__ float ub2[2][Hv];
    __shared__ float uab2[2][Hv];
    __shared__ float wa2s[Hv];
    __shared__ float partg[2][Cv][8];
    __shared__ float parta[2][Kv][8];
    __shared__ float exacts[2][Cv];
    __shared__ int   sel[2][Cv];
    __shared__ int   fsel[2][Kv];
    __shared__ int   fj[2][Kv];
    __shared__ float logit[2][Kv];
    __shared__ float attw[2][Kv];

    int bi0 = blockIdx.x * 2;
    int b   = bi0 >> 8;
    int tid = threadIdx.x;
    int lane = tid & 31;
    int warp = tid >> 5;

    // zero gate + att rows
    {
        float4 z = make_float4(0.f, 0.f, 0.f, 0.f);
        float4* gp = (float4*)(gate + bi0 * Nv);
        float4* ap = (float4*)(att  + bi0 * Nv);
        if (tid < 128) { gp[tid] = z; ap[tid] = z; }
    }

#pragma unroll
    for (int r = 0; r < 2; r++) {
        sc[r][tid]   = g_scores[(bi0 + r) * Nv + tid];
        ub2[r][tid]  = ub_g[(bi0 + r) * Hv + tid];
        uab2[r][tid] = uab_g[(bi0 + r) * Hv + tid];
    }
    wa2s[tid] = Wa2[tid];
    {
        int r = tid >> 7, d = tid & 127;
        si2[r][d] = s[(bi0 + r) * Dv + d];
    }
    __syncthreads();

    // approx top-12 per row (destructive)
    if (warp < 2) {
        int r = warp;
        for (int t = 0; t < Cv; t++) {
            float bv = -INFINITY; int bidx = Nv;
#pragma unroll
            for (int k = 0; k < 8; k++) {
                int q = k * 32 + lane;
                float v = sc[r][q];
                if (v > bv || (v == bv && q < bidx)) { bv = v; bidx = q; }
            }
#pragma unroll
            for (int off = 16; off > 0; off >>= 1) {
                float ov = __shfl_down_sync(0xffffffffu, bv, off);
                int   oi = __shfl_down_sync(0xffffffffu, bidx, off);
                if (ov > bv || (ov == bv && oi < bidx)) { bv = ov; bidx = oi; }
            }
            bidx = __shfl_sync(0xffffffffu, bidx, 0);
            if (lane == 0) { sel[r][t] = bidx; sc[r][bidx] = -INFINITY; }
            __syncwarp();
        }
    }
    __syncthreads();

    // gather candidates
#pragma unroll
    for (int k = 0; k < 12; k++) {
        int ii = k * 256 + tid;
        int d  = ii & 127;
        int rc = ii >> 7;
        int r  = (rc >= Cv) ? 1 : 0;
        int c  = rc - r * Cv;
        selT[d][rc] = s[(b * Nv + sel[r][c]) * Dv + d];
    }
    __syncthreads();

    // phase 1: exact gate rescore (12 cand/row), FFMA2
    int h = tid;
    {
        unsigned long long ag[2][6];
#pragma unroll
        for (int r = 0; r < 2; r++)
#pragma unroll
            for (int q = 0; q < 6; q++) ag[r][q] = 0ull;

        const float* pgm = Wg1 + Dv * Hv + h;
        const float* pgb = Wg1 + 2 * Dv * Hv + h;
#pragma unroll 2
        for (int d = 0; d < Dv; d++) {
            float wgm = pgm[d * Hv];
            float wgb = pgb[d * Hv];
            float cg0s = fmaf(si2[0][d], wgb, wgm);
            float cg1s = fmaf(si2[1][d], wgb, wgm);
            unsigned long long cg0 = pack2(cg0s, cg0s);
            unsigned long long cg1 = pack2(cg1s, cg1s);
            const ulonglong2* rowp = (const ulonglong2*)&selT[d][0];
#pragma unroll
            for (int q = 0; q < 3; q++) {
                ulonglong2 v0 = rowp[q];
                ffma2(ag[0][q * 2],     v0.x, cg0);
                ffma2(ag[0][q * 2 + 1], v0.y, cg0);
                ulonglong2 v1 = rowp[3 + q];
                ffma2(ag[1][q * 2],     v1.x, cg1);
                ffma2(ag[1][q * 2 + 1], v1.y, cg1);
            }
        }
#pragma unroll
        for (int r = 0; r < 2; r++) {
            float ug = ub2[r][h];          // includes bg1
            float wg = Wg2[h];
#pragma unroll
            for (int q = 0; q < 6; q++) {
                float2 g2 = unpack2(ag[r][q]);
#pragma unroll
                for (int half = 0; half < 2; half++) {
                    float gv = half ? g2.y : g2.x;
                    float vg = fmaxf(gv + ug, 0.f) * wg;
#pragma unroll
                    for (int off = 16; off > 0; off >>= 1)
                        vg += __shfl_xor_sync(0xffffffffu, vg, off);
                    if (lane == 0) partg[r][q * 2 + half][warp] = vg;
                }
            }
        }
    }
    __syncthreads();
    if (tid < 2 * Cv) {
        int r = tid / Cv, t = tid % Cv;
        float sSum = 0.f;
#pragma unroll
        for (int w8 = 0; w8 < 8; w8++) sSum += partg[r][t][w8];
        exacts[r][t] = sSum + bg2[0];
    }
    __syncthreads();

    // exact top-8 among 12
    if (warp < 2) {
        int r = warp;
        float v = (lane < Cv) ? exacts[r][lane] : -INFINITY;
        int jj  = (lane < Cv) ? sel[r][lane] : (1 << 30);
        int cc  = lane;
        for (int t = 0; t < Kv; t++) {
            float bv = v; int bj = jj; int bc = cc;
#pragma unroll
            for (int off = 16; off > 0; off >>= 1) {
                float ov = __shfl_down_sync(0xffffffffu, bv, off);
                int   oj = __shfl_down_sync(0xffffffffu, bj, off);
                int   oc = __shfl_down_sync(0xffffffffu, bc, off);
                if (ov > bv || (ov == bv && oj < bj)) { bv = ov; bj = oj; bc = oc; }
            }
            bc = __shfl_sync(0xffffffffu, bc, 0);
            bj = __shfl_sync(0xffffffffu, bj, 0);
            if (lane == 0) { fsel[r][t] = bc; fj[r][t] = bj; }
            if (cc == bc) v = -INFINITY;
        }
    }
    __syncthreads();

    // compact final-8 columns
#pragma unroll
    for (int k = 0; k < 8; k++) {
        int ii = k * 256 + tid;          // 0..2047
        int d  = ii & 127;
        int rc = ii >> 7;                // 0..15
        int r  = rc >> 3, t = rc & 7;
        selA[d][rc] = selT[d][r * Cv + fsel[r][t]];
    }
    __syncthreads();

    // phase 2: exact att logits for final 8
    {
        unsigned long long aa[2][4];
#pragma unroll
        for (int r = 0; r < 2; r++)
#pragma unroll
            for (int q = 0; q < 4; q++) aa[r][q] = 0ull;

        const float* pam = Wa1 + Dv * Hv + h;
        const float* pab = Wa1 + 2 * Dv * Hv + h;
#pragma unroll 2
        for (int d = 0; d < Dv; d++) {
            float wam = pam[d * Hv];
            float wab = pab[d * Hv];
            float ca0s = fmaf(si2[0][d], wab, wam);
            float ca1s = fmaf(si2[1][d], wab, wam);
            unsigned long long ca0 = pack2(ca0s, ca0s);
            unsigned long long ca1 = pack2(ca1s, ca1s);
            const ulonglong2* rowp = (const ulonglong2*)&selA[d][0];
#pragma unroll
            for (int q = 0; q < 2; q++) {
                ulonglong2 v0 = rowp[q];
                ffma2(aa[0][q * 2],     v0.x, ca0);
                ffma2(aa[0][q * 2 + 1], v0.y, ca0);
                ulonglong2 v1 = rowp[2 + q];
                ffma2(aa[1][q * 2],     v1.x, ca1);
                ffma2(aa[1][q * 2 + 1], v1.y, ca1);
            }
        }
#pragma unroll
        for (int r = 0; r < 2; r++) {
            float ua = uab2[r][h];        // includes ba1
            float wa = wa2s[h];
#pragma unroll
            for (int q = 0; q < 4; q++) {
                float2 a2 = unpack2(aa[r][q]);
#pragma unroll
                for (int half = 0; half < 2; half++) {
                    float av = half ? a2.y : a2.x;
                    float va = fmaxf(av + ua, 0.f) * wa;
#pragma unroll
                    for (int off = 16; off > 0; off >>= 1)
                        va += __shfl_xor_sync(0xffffffffu, va, off);
                    if (lane == 0) parta[r][q * 2 + half][warp] = va;
                }
            }
        }
    }
    __syncthreads();
    if (tid < 16) {
        int r = tid >> 3, t = tid & 7;
        float sSum = 0.f;
#pragma unroll
        for (int w8 = 0; w8 < 8; w8++) sSum += parta[r][t][w8];
        logit[r][t] = sSum + ba2[0];
    }
    __syncthreads();
    if (tid < 2) {
        float m = -INFINITY;
#pragma unroll
        for (int t = 0; t < Kv; t++) m = fmaxf(m, logit[tid][t]);
        float e[Kv], ssum = 0.f;
#pragma unroll
        for (int t = 0; t < Kv; t++) { e[t] = expf(logit[tid][t] - m); ssum += e[t]; }
#pragma unroll
        for (int t = 0; t < Kv; t++) attw[tid][t] = e[t] / ssum;
    }
    __syncthreads();

    if (tid < 16) {
        int r = tid >> 3, t = tid & 7;
        int js = fj[r][t];
        gate[(bi0 + r) * Nv + js] = 1.0f;
        att [(bi0 + r) * Nv + js] = attw[r][t];
    }
    if (tid < Dv) {
        int d = tid;
#pragma unroll
        for (int r = 0; r < 2; r++) {
            float cv = 0.f;
#pragma unroll
            for (int t = 0; t < Kv; t++)
                cv = fmaf(attw[r][t], selA[d][r * 8 + t], cv);
            ctx[(bi0 + r) * Dv + d] = cv;
        }
    }
}

// ---------------------------------------------------------------------------
extern "C" void kernel_launch(void* const* d_in, const int* in_sizes, int n_in,
                              void* d_out, int out_size)
{
    const float* s   = (const float*)d_in[0];
    const float* Wg1 = (const float*)d_in[1];
    const float* bg1 = (const float*)d_in[2];
    const float* Wg2 = (const float*)d_in[3];
    const float* bg2 = (const float*)d_in[4];
    const float* Wa1 = (const float*)d_in[5];
    const float* ba1 = (const float*)d_in[6];
    const float* Wa2 = (const float*)d_in[7];
    const float* ba2 = (const float*)d_in[8];

    float* out  = (float*)d_out;
    float* ctx  = out;
    float* gate = out + Bv * Nv * Dv;
    float* att  = gate + Bv * Nv * Nv;

    cudaFuncSetAttribute(gscore_kernel,
                         cudaFuncAttributeMaxDynamicSharedMemorySize, GS_SMEM);

    prep_kernel<<<ROWS / 2, 256>>>(s, Wg1);
    gscore_kernel<<<ROWS, 256, GS_SMEM>>>(s, Wg1, bg1, Wg2, Wa1, ba1);
    topk_kernel<<<ROWS / 2, 256>>>(s, Wg1, Wg2, bg2, Wa1, Wa2, ba2, ctx, gate, att);
}

// round 12
// speedup vs baseline: 1.2262x; 1.2262x over previous
#include <cuda_runtime.h>
#include <cuda_bf16.h>
#include <math.h>

// Problem constants
#define Bv 4
#define Nv 256
#define Dv 128
#define Hv 256
#define Kv 8
#define Cv 12
#define ROWS (Bv * Nv)      // 1024
#define TPAD 24

// Packed bf16 gate weights, quad layout: WPK4[d*64 + hgrp] = {wm(h0,h1), wb(h0,h1), wm(h2,h3), wb(h2,h3)}
// where hgrp = h/4 (0..63)
__device__ uint4 WPK4_buf[Dv * 64];   // 8192 uint4

// ---------------------------------------------------------------------------
// f32x2 packed helpers (sm_103a dual fp32 pipe)
// ---------------------------------------------------------------------------
__device__ __forceinline__ void ffma2(unsigned long long& d,
                                      unsigned long long a,
                                      unsigned long long b) {
    asm("fma.rn.f32x2 %0, %1, %2, %0;" : "+l"(d) : "l"(a), "l"(b));
}
__device__ __forceinline__ unsigned long long pack2(float x, float y) {
    unsigned long long r;
    asm("mov.b64 %0, {%1, %2};" : "=l"(r) : "f"(x), "f"(y));
    return r;
}
__device__ __forceinline__ float2 unpack2(unsigned long long v) {
    float2 r;
    asm("mov.b64 {%0, %1}, %2;" : "=f"(r.x), "=f"(r.y) : "l"(v));
    return r;
}

// ---------------------------------------------------------------------------
// MMA helpers
// ---------------------------------------------------------------------------
__device__ __forceinline__ void ldsm4(unsigned* r, unsigned addr) {
    asm volatile("ldmatrix.sync.aligned.m8n8.x4.shared.b16 {%0,%1,%2,%3}, [%4];"
                 : "=r"(r[0]), "=r"(r[1]), "=r"(r[2]), "=r"(r[3]) : "r"(addr));
}
__device__ __forceinline__ void ldsm4t(unsigned* r, unsigned addr) {
    asm volatile("ldmatrix.sync.aligned.m8n8.x4.trans.shared.b16 {%0,%1,%2,%3}, [%4];"
                 : "=r"(r[0]), "=r"(r[1]), "=r"(r[2]), "=r"(r[3]) : "r"(addr));
}
__device__ __forceinline__ void mma16816(float* d, const unsigned* a, unsigned b0, unsigned b1) {
    asm volatile("mma.sync.aligned.m16n8k16.row.col.f32.bf16.bf16.f32 "
                 "{%0,%1,%2,%3}, {%4,%5,%6,%7}, {%8,%9}, {%0,%1,%2,%3};"
                 : "+f"(d[0]), "+f"(d[1]), "+f"(d[2]), "+f"(d[3])
                 : "r"(a[0]), "r"(a[1]), "r"(a[2]), "r"(a[3]), "r"(b0), "r"(b1));
}

// ---------------------------------------------------------------------------
// Prelude: pack gate W_mid/W_bot to bf16 quads.
// ---------------------------------------------------------------------------
__global__ void pack_kernel(const float* __restrict__ Wg1)
{
    int idx = blockIdx.x * 256 + threadIdx.x;   // 0..8191
    int d  = idx >> 6;
    int hg = idx & 63;
    int h0 = hg * 4;
    float m0 = Wg1[(Dv + d) * Hv + h0];
    float m1 = Wg1[(Dv + d) * Hv + h0 + 1];
    float m2 = Wg1[(Dv + d) * Hv + h0 + 2];
    float m3 = Wg1[(Dv + d) * Hv + h0 + 3];
    float b0 = Wg1[(2 * Dv + d) * Hv + h0];
    float b1 = Wg1[(2 * Dv + d) * Hv + h0 + 1];
    float b2 = Wg1[(2 * Dv + d) * Hv + h0 + 2];
    float b3 = Wg1[(2 * Dv + d) * Hv + h0 + 3];
    __nv_bfloat162 m01 = __floats2bfloat162_rn(m0, m1);
    __nv_bfloat162 b01 = __floats2bfloat162_rn(b0, b1);
    __nv_bfloat162 m23 = __floats2bfloat162_rn(m2, m3);
    __nv_bfloat162 b23 = __floats2bfloat162_rn(b2, b3);
    uint4 v;
    v.x = *(unsigned*)&m01;
    v.y = *(unsigned*)&b01;
    v.z = *(unsigned*)&m23;
    v.w = *(unsigned*)&b23;
    WPK4_buf[idx] = v;
}

// ---------------------------------------------------------------------------
// smem layout
// ---------------------------------------------------------------------------
#define SJ 136   // padded bf16 stride for s tile (row = 272B)
#define CH 72    // padded bf16 stride for c tile (row = 144B)

#define OFS_A     0               // 69632: s tile [256][SJ] bf16
#define OFS_C     69632           // 2 c bufs x 18432; aliased post-GEMM:
                                  //   +0     : part  [2][2][256] f32 (8KB)
                                  //   +8192  : score [2][256] f32   (2KB)
                                  //   +12288 : selT  [128][TPAD] f32 (12KB)
                                  //   +24576 : partg [2][Cv][8] f32 (768B)
                                  //   +25344 : parta [2][Cv][8] f32 (768B)
#define OFS_UB    106496          // 2 x 256 f32 (Ug + bg1)
#define OFS_W2    108544          // 256 f32
#define OFS_SI    109568          // 2 x 128 f32
#define OFS_SIB   110592          // 256 uint (bf16x2, dup halves)
#define FUS_SMEM  111616

__global__ __launch_bounds__(256, 2) void fused_kernel(
    const float* __restrict__ s,
    const float* __restrict__ Wg1,
    const float* __restrict__ bg1,
    const float* __restrict__ Wg2,
    const float* __restrict__ bg2,
    const float* __restrict__ Wa1,
    const float* __restrict__ ba1,
    const float* __restrict__ Wa2,
    const float* __restrict__ ba2,
    float* __restrict__ ctx,
    float* __restrict__ gate,
    float* __restrict__ att)
{
    extern __shared__ unsigned char dynsm[];
    __nv_bfloat16* s_sm = (__nv_bfloat16*)dynsm;
    float* ub_sm    = (float*)(dynsm + OFS_UB);
    float* w2_sm    = (float*)(dynsm + OFS_W2);
    float* si_sm    = (float*)(dynsm + OFS_SI);
    unsigned* sib_sm = (unsigned*)(dynsm + OFS_SIB);
    // post-GEMM aliases of the C region
    float* part_sm  = (float*)(dynsm + OFS_C);              // [2][2][256]
    float* score_sm = (float*)(dynsm + OFS_C + 8192);       // [2][256]
    float (*selT)[TPAD] = (float (*)[TPAD])(dynsm + OFS_C + 12288);
    float* partg = (float*)(dynsm + OFS_C + 24576);         // [2][Cv][8]
    float* parta = (float*)(dynsm + OFS_C + 25344);

    __shared__ float exacts[2][Cv];
    __shared__ float alog[2][Cv];
    __shared__ int   sel[2][Cv];
    __shared__ int   fsel[2][Kv];
    __shared__ int   fj[2][Kv];
    __shared__ float logit[2][Kv];
    __shared__ float attw[2][Kv];

    int bi0 = blockIdx.x * 2;       // global row index (b*Nv + i0)
    int b   = bi0 >> 8;
    int tid = threadIdx.x;
    int lane = tid & 31;
    int warp = tid >> 5;

    // zero this block's gate + att rows
    {
        float4 z = make_float4(0.f, 0.f, 0.f, 0.f);
        float4* gp = (float4*)(gate + bi0 * Nv);
        float4* ap = (float4*)(att  + bi0 * Nv);
        if (tid < 128) { gp[tid] = z; ap[tid] = z; }
    }

    // si + small vectors
    {
        int r = tid >> 7, d = tid & 127;
        float v = s[(bi0 + r) * Dv + d];
        si_sm[r * 128 + d] = v;
        __nv_bfloat16 bv = __float2bfloat16(v);
        __nv_bfloat162 bb = __nv_bfloat162(bv, bv);
        sib_sm[r * 128 + d] = *(unsigned*)&bb;
    }
    w2_sm[tid] = Wg2[tid];
    float wa2_r = Wa2[tid];
    __syncthreads();

    // s_b -> bf16 padded smem (float4 loads, 8B stores)
    {
        const float4* sp4 = (const float4*)(s + b * Nv * Dv);
#pragma unroll
        for (int k = 0; k < 32; k++) {
            int t = k * 256 + tid;            // 0..8191 float4s
            int row = t >> 5;
            int c4  = t & 31;
            float4 v = sp4[t];
            __nv_bfloat162 lo = __floats2bfloat162_rn(v.x, v.y);
            __nv_bfloat162 hi = __floats2bfloat162_rn(v.z, v.w);
            uint2 pk;
            pk.x = *(unsigned*)&lo;
            pk.y = *(unsigned*)&hi;
            *(uint2*)((char*)s_sm + row * 272 + c4 * 8) = pk;
        }
    }

    // inline U for both MLPs, both rows (thread owns h = tid); fold biases in
    float ua0_r, ua1_r;
    {
        int h = tid;
        float ug0 = bg1[h], ug1 = ug0;
        float ua0 = ba1[h], ua1 = ua0;
#pragma unroll 8
        for (int d = 0; d < Dv; d++) {
            float wg = Wg1[d * Hv + h];
            float wa = Wa1[d * Hv + h];
            float s0 = si_sm[d];
            float s1 = si_sm[128 + d];
            ug0 = fmaf(s0, wg, ug0);
            ug1 = fmaf(s1, wg, ug1);
            ua0 = fmaf(s0, wa, ua0);
            ua1 = fmaf(s1, wa, ua1);
        }
        ub_sm[h]       = ug0;
        ub_sm[256 + h] = ug1;
        ua0_r = ua0;
        ua1_r = ua1;
    }

    // ---------------- pipelined GEMM phase ----------------
    const unsigned sbase  = (unsigned)__cvta_generic_to_shared(s_sm);
    const unsigned cbase0 = (unsigned)__cvta_generic_to_shared(dynsm + OFS_C);
    int wm_ = (warp & 3) * 64;
    int wn  = (warp >> 2) * 32;
    int aRow  = wm_ + (lane & 15);
    int aColB = ((lane >> 4) << 3) * 2;
    int bK    = lane & 15;
    int bH    = wn + ((lane >> 4) << 3);

    int bld_d  = tid >> 4;            // 0..15 (d-base within each k-group of 16 rows)
    int bld_hq = tid & 15;            // 0..15 (h quad within 64-h chunk)

    // per-thread running score partials (quad-lane h-slices)
    float sreg[2][4][2];
#pragma unroll
    for (int ii = 0; ii < 2; ii++)
#pragma unroll
        for (int mt = 0; mt < 4; mt++) { sreg[ii][mt][0] = 0.f; sreg[ii][mt][1] = 0.f; }

    // initial build: round 0 (hc=0, ii=0) into buf 0
    {
        unsigned char* cbuf = dynsm + OFS_C;
#pragma unroll
        for (int k = 0; k < 8; k++) {
            int dd = k * 16 + bld_d;
            uint4 wv = WPK4_buf[dd * 64 + bld_hq];
            __nv_bfloat162 sib = *(__nv_bfloat162*)&sib_sm[dd];
            __nv_bfloat162 m01 = *(__nv_bfloat162*)&wv.x;
            __nv_bfloat162 b01 = *(__nv_bfloat162*)&wv.y;
            __nv_bfloat162 m23 = *(__nv_bfloat162*)&wv.z;
            __nv_bfloat162 b23 = *(__nv_bfloat162*)&wv.w;
            __nv_bfloat162 c01 = __hfma2(sib, b01, m01);
            __nv_bfloat162 c23 = __hfma2(sib, b23, m23);
            uint2 pk;
            pk.x = *(unsigned*)&c01;
            pk.y = *(unsigned*)&c23;
            *(uint2*)(cbuf + dd * 144 + bld_hq * 8) = pk;
        }
    }
    __syncthreads();

#pragma unroll 1
    for (int r = 0; r < 8; r++) {
        int hc = r >> 1, ii = r & 1;
        int nxt = r + 1;

        // prefetch first half of next round's W quads (regs)
        uint4 w4[4];
        if (nxt < 8) {
            int hcN = nxt >> 1;
#pragma unroll
            for (int k = 0; k < 4; k++) {
                int dd = k * 16 + bld_d;
                w4[k] = WPK4_buf[dd * 64 + hcN * 16 + bld_hq];
            }
        }

        // MMA on current buffer
        float acc[16][4];
#pragma unroll
        for (int q = 0; q < 16; q++) { acc[q][0]=0.f; acc[q][1]=0.f; acc[q][2]=0.f; acc[q][3]=0.f; }

        unsigned cb = cbase0 + (unsigned)((r & 1) * 18432);
#pragma unroll
        for (int ks = 0; ks < 8; ks++) {
            unsigned a[4][4], bq[2][4];
#pragma unroll
            for (int mt = 0; mt < 4; mt++) {
                unsigned addr = sbase + (unsigned)((aRow + mt * 16) * (SJ * 2) + ks * 32) + aColB;
                ldsm4(a[mt], addr);
            }
#pragma unroll
            for (int nt = 0; nt < 2; nt++) {
                unsigned addr = cb + (unsigned)((ks * 16 + bK) * (CH * 2) + (bH + nt * 16) * 2);
                ldsm4t(bq[nt], addr);
            }
#pragma unroll
            for (int mt = 0; mt < 4; mt++)
#pragma unroll
                for (int n8 = 0; n8 < 4; n8++)
                    mma16816(acc[mt * 4 + n8], a[mt], bq[n8 >> 1][(n8 & 1) * 2], bq[n8 >> 1][(n8 & 1) * 2 + 1]);
        }

        // commit build of next round's c tile (first 4 quads from regs, last 4 inline)
        if (nxt < 8) {
            int iiN = nxt & 1;
            int hcN = nxt >> 1;
            unsigned char* cbuf = dynsm + OFS_C + (nxt & 1) * 18432;
#pragma unroll
            for (int k = 0; k < 4; k++) {
                int dd = k * 16 + bld_d;
                __nv_bfloat162 sib = *(__nv_bfloat162*)&sib_sm[iiN * 128 + dd];
                __nv_bfloat162 m01 = *(__nv_bfloat162*)&w4[k].x;
                __nv_bfloat162 b01 = *(__nv_bfloat162*)&w4[k].y;
                __nv_bfloat162 m23 = *(__nv_bfloat162*)&w4[k].z;
                __nv_bfloat162 b23 = *(__nv_bfloat162*)&w4[k].w;
                __nv_bfloat162 c01 = __hfma2(sib, b01, m01);
                __nv_bfloat162 c23 = __hfma2(sib, b23, m23);
                uint2 pk;
                pk.x = *(unsigned*)&c01;
                pk.y = *(unsigned*)&c23;
                *(uint2*)(cbuf + dd * 144 + bld_hq * 8) = pk;
            }
#pragma unroll
            for (int k = 4; k < 8; k++) {
                int dd = k * 16 + bld_d;
                uint4 wv = WPK4_buf[dd * 64 + hcN * 16 + bld_hq];
                __nv_bfloat162 sib = *(__nv_bfloat162*)&sib_sm[iiN * 128 + dd];
                __nv_bfloat162 m01 = *(__nv_bfloat162*)&wv.x;
                __nv_bfloat162 b01 = *(__nv_bfloat162*)&wv.y;
                __nv_bfloat162 m23 = *(__nv_bfloat162*)&wv.z;
                __nv_bfloat162 b23 = *(__nv_bfloat162*)&wv.w;
                __nv_bfloat162 c01 = __hfma2(sib, b01, m01);
                __nv_bfloat162 c23 = __hfma2(sib, b23, m23);
                uint2 pk;
                pk.x = *(unsigned*)&c01;
                pk.y = *(unsigned*)&c23;
                *(uint2*)(cbuf + dd * 144 + bld_hq * 8) = pk;
            }
        }

        // epilogue: relu + dot W2 into register partials (no shfl/atomics)
        {
            int hb = hc * 64 + wn + (lane & 3) * 2;
            const float2* u2p = (const float2*)(ub_sm + ii * 256);
            const float2* w2p = (const float2*)w2_sm;
            float2 uu[4], ww[4];
#pragma unroll
            for (int n8 = 0; n8 < 4; n8++) {
                uu[n8] = u2p[(hb + n8 * 8) >> 1];
                ww[n8] = w2p[(hb + n8 * 8) >> 1];
            }
#pragma unroll
            for (int mt = 0; mt < 4; mt++) {
                float p0 = sreg[ii][mt][0];
                float p1 = sreg[ii][mt][1];
#pragma unroll
                for (int n8 = 0; n8 < 4; n8++) {
                    const float* A = acc[mt * 4 + n8];
                    p0 = fmaf(fmaxf(A[0] + uu[n8].x, 0.f), ww[n8].x, p0);
                    p0 = fmaf(fmaxf(A[1] + uu[n8].y, 0.f), ww[n8].y, p0);
                    p1 = fmaf(fmaxf(A[2] + uu[n8].x, 0.f), ww[n8].x, p1);
                    p1 = fmaf(fmaxf(A[3] + uu[n8].y, 0.f), ww[n8].y, p1);
                }
                sreg[ii][mt][0] = p0;
                sreg[ii][mt][1] = p1;
            }
        }
        __syncthreads();
    }

    // final reduction: quad-reduce sreg, write per-nwarp parts (alias C, now dead)
    {
        int nw = wn >> 5;   // 0 or 1
#pragma unroll
        for (int ii = 0; ii < 2; ii++)
#pragma unroll
            for (int mt = 0; mt < 4; mt++)
#pragma unroll
                for (int half = 0; half < 2; half++) {
                    float v = sreg[ii][mt][half];
                    v += __shfl_xor_sync(0xffffffffu, v, 1);
                    v += __shfl_xor_sync(0xffffffffu, v, 2);
                    if ((lane & 3) == 0) {
                        int j = wm_ + (lane >> 2) + mt * 16 + half * 8;
                        part_sm[(ii * 2 + nw) * 256 + j] = v;
                    }
                }
    }
    __syncthreads();
    {
        float b2v = bg2[0];
        score_sm[tid]       = part_sm[tid]        + part_sm[256 + tid] + b2v;
        score_sm[256 + tid] = part_sm[512 + tid]  + part_sm[768 + tid] + b2v;
    }
    __syncthreads();

    // ---------------- selection + rescore phase ----------------
    // approx top-12 per row directly on score_sm (destructive)
    if (warp < 2) {
        int r = warp;
        float* scr = score_sm + r * 256;
        for (int t = 0; t < Cv; t++) {
            float bv = -INFINITY; int bidx = Nv;
#pragma unroll
            for (int k = 0; k < 8; k++) {
                int q = k * 32 + lane;
                float v = scr[q];
                if (v > bv || (v == bv && q < bidx)) { bv = v; bidx = q; }
            }
#pragma unroll
            for (int off = 16; off > 0; off >>= 1) {
                float ov = __shfl_down_sync(0xffffffffu, bv, off);
                int   oi = __shfl_down_sync(0xffffffffu, bidx, off);
                if (ov > bv || (ov == bv && oi < bidx)) { bv = ov; bidx = oi; }
            }
            bidx = __shfl_sync(0xffffffffu, bidx, 0);
            if (lane == 0) { sel[r][t] = bidx; scr[bidx] = -INFINITY; }
            __syncwarp();
        }
    }
    __syncthreads();

    // gather candidate s_j rows into selT
#pragma unroll
    for (int k = 0; k < 12; k++) {
        int ii = k * 256 + tid;           // 0..3071
        int d  = ii & 127;
        int rc = ii >> 7;                 // 0..23
        int r  = (rc >= Cv) ? 1 : 0;
        int c  = rc - r * Cv;
        selT[d][rc] = s[(b * Nv + sel[r][c]) * Dv + d];
    }
    __syncthreads();

    // fused exact fp32 rescore (gate + att) for all 24 candidates, FFMA2
    int h = tid;
    unsigned long long ag[2][6], aa[2][6];
#pragma unroll
    for (int r = 0; r < 2; r++)
#pragma unroll
        for (int q = 0; q < 6; q++) { ag[r][q] = 0ull; aa[r][q] = 0ull; }

    const float* pgm = Wg1 + Dv * Hv + h;
    const float* pgb = Wg1 + 2 * Dv * Hv + h;
    const float* pam = Wa1 + Dv * Hv + h;
    const float* pab = Wa1 + 2 * Dv * Hv + h;

#pragma unroll 2
    for (int d = 0; d < Dv; d++) {
        float wgm = pgm[d * Hv];
        float wgb = pgb[d * Hv];
        float wam = pam[d * Hv];
        float wab = pab[d * Hv];
        float s0 = si_sm[d], s1 = si_sm[128 + d];
        float cg0s = fmaf(s0, wgb, wgm);
        float cg1s = fmaf(s1, wgb, wgm);
        float ca0s = fmaf(s0, wab, wam);
        float ca1s = fmaf(s1, wab, wam);
        unsigned long long cg0 = pack2(cg0s, cg0s);
        unsigned long long cg1 = pack2(cg1s, cg1s);
        unsigned long long ca0 = pack2(ca0s, ca0s);
        unsigned long long ca1 = pack2(ca1s, ca1s);

        const ulonglong2* rowp = (const ulonglong2*)&selT[d][0];
#pragma unroll
        for (int q = 0; q < 3; q++) {
            ulonglong2 v0 = rowp[q];
            ffma2(ag[0][q * 2],     v0.x, cg0);
            ffma2(ag[0][q * 2 + 1], v0.y, cg0);
            ffma2(aa[0][q * 2],     v0.x, ca0);
            ffma2(aa[0][q * 2 + 1], v0.y, ca0);
            ulonglong2 v1 = rowp[3 + q];
            ffma2(ag[1][q * 2],     v1.x, cg1);
            ffma2(ag[1][q * 2 + 1], v1.y, cg1);
            ffma2(aa[1][q * 2],     v1.x, ca1);
            ffma2(aa[1][q * 2 + 1], v1.y, ca1);
        }
    }

    // relu + dot W2 for both MLPs, warp reduce, stash partials
#pragma unroll
    for (int r = 0; r < 2; r++) {
        float ug = ub_sm[r * 256 + h];            // includes bg1
        float ua = (r == 0) ? ua0_r : ua1_r;      // includes ba1
        float wg = w2_sm[h];
        float wa = wa2_r;
#pragma unroll
        for (int q = 0; q < 6; q++) {
            float2 g2 = unpack2(ag[r][q]);
            float2 a2 = unpack2(aa[r][q]);
#pragma unroll
            for (int half = 0; half < 2; half++) {
                int t = q * 2 + half;
                float gv = half ? g2.y : g2.x;
                float av = half ? a2.y : a2.x;
                float vg = fmaxf(gv + ug, 0.f) * wg;
                float va = fmaxf(av + ua, 0.f) * wa;
#pragma unroll
                for (int off = 16; off > 0; off >>= 1) {
                    vg += __shfl_xor_sync(0xffffffffu, vg, off);
                    va += __shfl_xor_sync(0xffffffffu, va, off);
                }
                if (lane == 0) {
                    partg[(r * Cv + t) * 8 + warp] = vg;
                    parta[(r * Cv + t) * 8 + warp] = va;
                }
            }
        }
    }
    __syncthreads();

    // block sums
    if (tid < 2 * Cv) {
        int r = tid / Cv, t = tid % Cv;
        float sSum = 0.f;
#pragma unroll
        for (int w8 = 0; w8 < 8; w8++) sSum += partg[(r * Cv + t) * 8 + w8];
        exacts[r][t] = sSum + bg2[0];
    } else if (tid >= 64 && tid < 64 + 2 * Cv) {
        int k = tid - 64;
        int r = k / Cv, t = k % Cv;
        float sSum = 0.f;
#pragma unroll
        for (int w8 = 0; w8 < 8; w8++) sSum += parta[(r * Cv + t) * 8 + w8];
        alog[r][t] = sSum + ba2[0];
    }
    __syncthreads();

    // exact top-8 among 12 candidates (tie -> lowest original j)
    if (warp < 2) {
        int r = warp;
        float v = (lane < Cv) ? exacts[r][lane] : -INFINITY;
        int jj  = (lane < Cv) ? sel[r][lane] : (1 << 30);
        int cc  = lane;
        for (int t = 0; t < Kv; t++) {
            float bv = v; int bj = jj; int bc = cc;
#pragma unroll
            for (int off = 16; off > 0; off >>= 1) {
                float ov = __shfl_down_sync(0xffffffffu, bv, off);
                int   oj = __shfl_down_sync(0xffffffffu, bj, off);
                int   oc = __shfl_down_sync(0xffffffffu, bc, off);
                if (ov > bv || (ov == bv && oj < bj)) { bv = ov; bj = oj; bc = oc; }
            }
            bc = __shfl_sync(0xffffffffu, bc, 0);
            bj = __shfl_sync(0xffffffffu, bj, 0);
            if (lane == 0) { fsel[r][t] = bc; fj[r][t] = bj; }
            if (cc == bc) v = -INFINITY;
        }
    }
    __syncthreads();

    if (tid < 16) {
        int r = tid >> 3, t = tid & 7;
        logit[r][t] = alog[r][fsel[r][t]];
    }
    __syncthreads();
    if (tid < 2) {
        float m = -INFINITY;
#pragma unroll
        for (int t = 0; t < Kv; t++) m = fmaxf(m, logit[tid][t]);
        float e[Kv], ssum = 0.f;
#pragma unroll
        for (int t = 0; t < Kv; t++) { e[t] = expf(logit[tid][t] - m); ssum += e[t]; }
#pragma unroll
        for (int t = 0; t < Kv; t++) attw[tid][t] = e[t] / ssum;
    }
    __syncthreads();

    if (tid < 16) {
        int r = tid >> 3, t = tid & 7;
        int js = fj[r][t];
        gate[(bi0 + r) * Nv + js] = 1.0f;
        att [(bi0 + r) * Nv + js] = attw[r][t];
    }
    if (tid < Dv) {
        int d = tid;
#pragma unroll
        for (int r = 0; r < 2; r++) {
            float cv = 0.f;
#pragma unroll
            for (int t = 0; t < Kv; t++)
                cv = fmaf(attw[r][t], selT[d][r * Cv + fsel[r][t]], cv);
            ctx[(bi0 + r) * Dv + d] = cv;
        }
    }
}

// ---------------------------------------------------------------------------
extern "C" void kernel_launch(void* const* d_in, const int* in_sizes, int n_in,
                              void* d_out, int out_size)
{
    const float* s   = (const float*)d_in[0];
    const float* Wg1 = (const float*)d_in[1];
    const float* bg1 = (const float*)d_in[2];
    const float* Wg2 = (const float*)d_in[3];
    const float* bg2 = (const float*)d_in[4];
    const float* Wa1 = (const float*)d_in[5];
    const float* ba1 = (const float*)d_in[6];
    const float* Wa2 = (const float*)d_in[7];
    const float* ba2 = (const float*)d_in[8];

    float* out  = (float*)d_out;
    float* ctx  = out;
    float* gate = out + Bv * Nv * Dv;
    float* att  = gate + Bv * Nv * Nv;

    cudaFuncSetAttribute(fused_kernel,
                         cudaFuncAttributeMaxDynamicSharedMemorySize, FUS_SMEM);

    pack_kernel<<<32, 256>>>(Wg1);
    fused_kernel<<<ROWS / 2, 256, FUS_SMEM>>>(s, Wg1, bg1, Wg2, bg2,
                                              Wa1, ba1, Wa2, ba2, ctx, gate, att);
}

// round 13
// speedup vs baseline: 1.2309x; 1.0038x over previous
#include <cuda_runtime.h>
#include <cuda_bf16.h>
#include <math.h>

// Problem constants
#define Bv 4
#define Nv 256
#define Dv 128
#define Hv 256
#define Kv 8
#define Cv 12
#define ROWS (Bv * Nv)      // 1024
#define TPAD 24

// Packed bf16 gate weights, quad layout: WPK4[d*64 + hgrp] = {wm(h0,h1), wb(h0,h1), wm(h2,h3), wb(h2,h3)}
__device__ uint4 WPK4_buf[Dv * 64];        // 8192 uint4
__device__ uint4 s_img4[Bv * Nv * 17];     // bf16 A images, 272B rows (last 16B pad uninit)
__device__ float ub_g[ROWS * Hv];          // Ug + bg1
__device__ float uab_g[ROWS * Hv];         // Ua + ba1

// ---------------------------------------------------------------------------
// f32x2 packed helpers (sm_103a dual fp32 pipe)
// ---------------------------------------------------------------------------
__device__ __forceinline__ void ffma2(unsigned long long& d,
                                      unsigned long long a,
                                      unsigned long long b) {
    asm("fma.rn.f32x2 %0, %1, %2, %0;" : "+l"(d) : "l"(a), "l"(b));
}
__device__ __forceinline__ unsigned long long pack2(float x, float y) {
    unsigned long long r;
    asm("mov.b64 %0, {%1, %2};" : "=l"(r) : "f"(x), "f"(y));
    return r;
}
__device__ __forceinline__ float2 unpack2(unsigned long long v) {
    float2 r;
    asm("mov.b64 {%0, %1}, %2;" : "=f"(r.x), "=f"(r.y) : "l"(v));
    return r;
}

// ---------------------------------------------------------------------------
// MMA helpers
// ---------------------------------------------------------------------------
__device__ __forceinline__ void ldsm4(unsigned* r, unsigned addr) {
    asm volatile("ldmatrix.sync.aligned.m8n8.x4.shared.b16 {%0,%1,%2,%3}, [%4];"
                 : "=r"(r[0]), "=r"(r[1]), "=r"(r[2]), "=r"(r[3]) : "r"(addr));
}
__device__ __forceinline__ void ldsm4t(unsigned* r, unsigned addr) {
    asm volatile("ldmatrix.sync.aligned.m8n8.x4.trans.shared.b16 {%0,%1,%2,%3}, [%4];"
                 : "=r"(r[0]), "=r"(r[1]), "=r"(r[2]), "=r"(r[3]) : "r"(addr));
}
__device__ __forceinline__ void mma16816(float* d, const unsigned* a, unsigned b0, unsigned b1) {
    asm volatile("mma.sync.aligned.m16n8k16.row.col.f32.bf16.bf16.f32 "
                 "{%0,%1,%2,%3}, {%4,%5,%6,%7}, {%8,%9}, {%0,%1,%2,%3};"
                 : "+f"(d[0]), "+f"(d[1]), "+f"(d[2]), "+f"(d[3])
                 : "r"(a[0]), "r"(a[1]), "r"(a[2]), "r"(a[3]), "r"(b0), "r"(b1));
}

// ---------------------------------------------------------------------------
// prep: WPK4 pack + bf16 A image + U (both MLPs, biases folded) + output zero.
// grid = 256 blocks x 4 rows.
// ---------------------------------------------------------------------------
__global__ __launch_bounds__(256) void prep_kernel(
    const float* __restrict__ s,
    const float* __restrict__ Wg1,
    const float* __restrict__ bg1,
    const float* __restrict__ Wa1,
    const float* __restrict__ ba1,
    float* __restrict__ gate,
    float* __restrict__ att)
{
    __shared__ float si[4][Dv];
    int bi0 = blockIdx.x * 4;
    int tid = threadIdx.x;

    // load 4 s rows (512 floats, 2 per thread)
    {
        int r = tid >> 6, d2 = (tid & 63) * 2;
        float2 v = *(const float2*)&s[(bi0 + r) * Dv + d2];
        si[r][d2] = v.x;
        si[r][d2 + 1] = v.y;
    }

    // zero gate + att rows (4 rows x 256 floats each = 256 float4 per array)
    {
        float4 z = make_float4(0.f, 0.f, 0.f, 0.f);
        ((float4*)(gate + bi0 * Nv))[tid] = z;
        ((float4*)(att  + bi0 * Nv))[tid] = z;
    }

    // WPK4: 32 entries per block
    if (tid < 32) {
        int idx = blockIdx.x * 32 + tid;
        int d  = idx >> 6;
        int hg = idx & 63;
        int h0 = hg * 4;
        float m0 = Wg1[(Dv + d) * Hv + h0];
        float m1 = Wg1[(Dv + d) * Hv + h0 + 1];
        float m2 = Wg1[(Dv + d) * Hv + h0 + 2];
        float m3 = Wg1[(Dv + d) * Hv + h0 + 3];
        float b0 = Wg1[(2 * Dv + d) * Hv + h0];
        float b1 = Wg1[(2 * Dv + d) * Hv + h0 + 1];
        float b2 = Wg1[(2 * Dv + d) * Hv + h0 + 2];
        float b3 = Wg1[(2 * Dv + d) * Hv + h0 + 3];
        __nv_bfloat162 m01 = __floats2bfloat162_rn(m0, m1);
        __nv_bfloat162 b01 = __floats2bfloat162_rn(b0, b1);
        __nv_bfloat162 m23 = __floats2bfloat162_rn(m2, m3);
        __nv_bfloat162 b23 = __floats2bfloat162_rn(b2, b3);
        uint4 v;
        v.x = *(unsigned*)&m01;
        v.y = *(unsigned*)&b01;
        v.z = *(unsigned*)&m23;
        v.w = *(unsigned*)&b23;
        WPK4_buf[idx] = v;
    }
    __syncthreads();

    // A image: 4 rows x 32 uint2 (bf16x4 chunks)
    if (tid < 128) {
        int r = tid >> 5, c4 = tid & 31;
        float4 v = *(const float4*)&si[r][c4 * 4];
        __nv_bfloat162 lo = __floats2bfloat162_rn(v.x, v.y);
        __nv_bfloat162 hi = __floats2bfloat162_rn(v.z, v.w);
        uint2 pk;
        pk.x = *(unsigned*)&lo;
        pk.y = *(unsigned*)&hi;
        ((uint2*)s_img4)[(bi0 + r) * 34 + c4] = pk;
    }

    // U for 4 rows, both MLPs: thread owns (mlp, h-pair)
    {
        int mlp = tid >> 7;
        int h0  = (tid & 127) * 2;
        const float* W1 = mlp ? Wa1 : Wg1;
        const float* b1 = mlp ? ba1 : bg1;
        float2 bias = *(const float2*)&b1[h0];
        unsigned long long acc[4];
        unsigned long long bp = pack2(bias.x, bias.y);
#pragma unroll
        for (int r = 0; r < 4; r++) acc[r] = bp;
#pragma unroll 4
        for (int d = 0; d < Dv; d++) {
            unsigned long long w = *(const unsigned long long*)&W1[d * Hv + h0];
#pragma unroll
            for (int r = 0; r < 4; r++) {
                float sv = si[r][d];
                ffma2(acc[r], w, pack2(sv, sv));
            }
        }
        float* dst = mlp ? uab_g : ub_g;
#pragma unroll
        for (int r = 0; r < 4; r++) {
            float2 u2 = unpack2(acc[r]);
            *(float2*)&dst[(bi0 + r) * Hv + h0] = u2;
        }
    }
}

// ---------------------------------------------------------------------------
// smem layout (identical to the 135.9us kernel)
// ---------------------------------------------------------------------------
#define SJ 136   // padded bf16 stride for s tile (row = 272B)
#define CH 72    // padded bf16 stride for c tile (row = 144B)

#define OFS_A     0               // 69632: s tile [256][SJ] bf16
#define OFS_C     69632           // 2 c bufs x 18432; aliased post-GEMM
#define OFS_UB    106496          // 2 x 256 f32 (Ug + bg1)
#define OFS_W2    108544          // 256 f32
#define OFS_SI    109568          // 2 x 128 f32
#define OFS_SIB   110592          // 256 uint (bf16x2, dup halves)
#define FUS_SMEM  111616

__global__ __launch_bounds__(256, 2) void fused_kernel(
    const float* __restrict__ s,
    const float* __restrict__ Wg1,
    const float* __restrict__ bg2,
    const float* __restrict__ Wg2,
    const float* __restrict__ Wa1,
    const float* __restrict__ Wa2,
    const float* __restrict__ ba2,
    float* __restrict__ ctx,
    float* __restrict__ gate,
    float* __restrict__ att)
{
    extern __shared__ unsigned char dynsm[];
    __nv_bfloat16* s_sm = (__nv_bfloat16*)dynsm;
    float* ub_sm    = (float*)(dynsm + OFS_UB);
    float* w2_sm    = (float*)(dynsm + OFS_W2);
    float* si_sm    = (float*)(dynsm + OFS_SI);
    unsigned* sib_sm = (unsigned*)(dynsm + OFS_SIB);
    // post-GEMM aliases of the C region
    float* part_sm  = (float*)(dynsm + OFS_C);              // [2][2][256]
    float* score_sm = (float*)(dynsm + OFS_C + 8192);       // [2][256]
    float (*selT)[TPAD] = (float (*)[TPAD])(dynsm + OFS_C + 12288);
    float* partg = (float*)(dynsm + OFS_C + 24576);         // [2][Cv][8]
    float* parta = (float*)(dynsm + OFS_C + 25344);

    __shared__ float exacts[2][Cv];
    __shared__ float alog[2][Cv];
    __shared__ int   sel[2][Cv];
    __shared__ int   fsel[2][Kv];
    __shared__ int   fj[2][Kv];
    __shared__ float logit[2][Kv];
    __shared__ float attw[2][Kv];

    int bi0 = blockIdx.x * 2;       // global row index (b*Nv + i0)
    int b   = bi0 >> 8;
    int tid = threadIdx.x;
    int lane = tid & 31;
    int warp = tid >> 5;

    // si + small vectors + precomputed U
    {
        int r = tid >> 7, d = tid & 127;
        float v = s[(bi0 + r) * Dv + d];
        si_sm[r * 128 + d] = v;
        __nv_bfloat16 bv = __float2bfloat16(v);
        __nv_bfloat162 bb = __nv_bfloat162(bv, bv);
        sib_sm[r * 128 + d] = *(unsigned*)&bb;
    }
    w2_sm[tid] = Wg2[tid];
    float wa2_r = Wa2[tid];
    ub_sm[tid]       = ub_g[bi0 * Hv + tid];
    ub_sm[256 + tid] = ub_g[(bi0 + 1) * Hv + tid];
    float ua0_r = uab_g[bi0 * Hv + tid];
    float ua1_r = uab_g[(bi0 + 1) * Hv + tid];
    __syncthreads();

    // A tile: raw copy of pre-converted bf16 image (17 uint4/thread)
    {
        const uint4* src = s_img4 + (size_t)b * 256 * 17;
        uint4* dst = (uint4*)(dynsm + OFS_A);
#pragma unroll
        for (int k = 0; k < 17; k++)
            dst[k * 256 + tid] = src[k * 256 + tid];
    }

    int bld_d  = tid >> 4;            // 0..15
    int bld_hq = tid & 15;            // 0..15

    // initial build: round 0 (hc=0, ii=0) into buf 0
    {
        unsigned char* cbuf = dynsm + OFS_C;
#pragma unroll
        for (int k = 0; k < 8; k++) {
            int dd = k * 16 + bld_d;
            uint4 wv = WPK4_buf[dd * 64 + bld_hq];
            __nv_bfloat162 sib = *(__nv_bfloat162*)&sib_sm[dd];
            __nv_bfloat162 m01 = *(__nv_bfloat162*)&wv.x;
            __nv_bfloat162 b01 = *(__nv_bfloat162*)&wv.y;
            __nv_bfloat162 m23 = *(__nv_bfloat162*)&wv.z;
            __nv_bfloat162 b23 = *(__nv_bfloat162*)&wv.w;
            __nv_bfloat162 c01 = __hfma2(sib, b01, m01);
            __nv_bfloat162 c23 = __hfma2(sib, b23, m23);
            uint2 pk;
            pk.x = *(unsigned*)&c01;
            pk.y = *(unsigned*)&c23;
            *(uint2*)(cbuf + dd * 144 + bld_hq * 8) = pk;
        }
    }
    __syncthreads();

    // ---------------- pipelined GEMM phase ----------------
    const unsigned sbase  = (unsigned)__cvta_generic_to_shared(s_sm);
    const unsigned cbase0 = (unsigned)__cvta_generic_to_shared(dynsm + OFS_C);
    int wm_ = (warp & 3) * 64;
    int wn  = (warp >> 2) * 32;
    int aRow  = wm_ + (lane & 15);
    int aColB = ((lane >> 4) << 3) * 2;
    int bK    = lane & 15;
    int bH    = wn + ((lane >> 4) << 3);

    // per-thread running score partials (quad-lane h-slices)
    float sreg[2][4][2];
#pragma unroll
    for (int ii = 0; ii < 2; ii++)
#pragma unroll
        for (int mt = 0; mt < 4; mt++) { sreg[ii][mt][0] = 0.f; sreg[ii][mt][1] = 0.f; }

#pragma unroll 1
    for (int r = 0; r < 8; r++) {
        int hc = r >> 1, ii = r & 1;
        int nxt = r + 1;

        // prefetch first half of next round's W quads (regs)
        uint4 w4[4];
        if (nxt < 8) {
            int hcN = nxt >> 1;
#pragma unroll
            for (int k = 0; k < 4; k++) {
                int dd = k * 16 + bld_d;
                w4[k] = WPK4_buf[dd * 64 + hcN * 16 + bld_hq];
            }
        }

        // MMA on current buffer
        float acc[16][4];
#pragma unroll
        for (int q = 0; q < 16; q++) { acc[q][0]=0.f; acc[q][1]=0.f; acc[q][2]=0.f; acc[q][3]=0.f; }

        unsigned cb = cbase0 + (unsigned)((r & 1) * 18432);
#pragma unroll
        for (int ks = 0; ks < 8; ks++) {
            unsigned a[4][4], bq[2][4];
#pragma unroll
            for (int mt = 0; mt < 4; mt++) {
                unsigned addr = sbase + (unsigned)((aRow + mt * 16) * (SJ * 2) + ks * 32) + aColB;
                ldsm4(a[mt], addr);
            }
#pragma unroll
            for (int nt = 0; nt < 2; nt++) {
                unsigned addr = cb + (unsigned)((ks * 16 + bK) * (CH * 2) + (bH + nt * 16) * 2);
                ldsm4t(bq[nt], addr);
            }
#pragma unroll
            for (int mt = 0; mt < 4; mt++)
#pragma unroll
                for (int n8 = 0; n8 < 4; n8++)
                    mma16816(acc[mt * 4 + n8], a[mt], bq[n8 >> 1][(n8 & 1) * 2], bq[n8 >> 1][(n8 & 1) * 2 + 1]);
        }

        // commit build of next round's c tile (first 4 quads from regs, last 4 inline)
        if (nxt < 8) {
            int iiN = nxt & 1;
            int hcN = nxt >> 1;
            unsigned char* cbuf = dynsm + OFS_C + (nxt & 1) * 18432;
#pragma unroll
            for (int k = 0; k < 4; k++) {
                int dd = k * 16 + bld_d;
                __nv_bfloat162 sib = *(__nv_bfloat162*)&sib_sm[iiN * 128 + dd];
                __nv_bfloat162 m01 = *(__nv_bfloat162*)&w4[k].x;
                __nv_bfloat162 b01 = *(__nv_bfloat162*)&w4[k].y;
                __nv_bfloat162 m23 = *(__nv_bfloat162*)&w4[k].z;
                __nv_bfloat162 b23 = *(__nv_bfloat162*)&w4[k].w;
                __nv_bfloat162 c01 = __hfma2(sib, b01, m01);
                __nv_bfloat162 c23 = __hfma2(sib, b23, m23);
                uint2 pk;
                pk.x = *(unsigned*)&c01;
                pk.y = *(unsigned*)&c23;
                *(uint2*)(cbuf + dd * 144 + bld_hq * 8) = pk;
            }
#pragma unroll
            for (int k = 4; k < 8; k++) {
                int dd = k * 16 + bld_d;
                uint4 wv = WPK4_buf[dd * 64 + hcN * 16 + bld_hq];
                __nv_bfloat162 sib = *(__nv_bfloat162*)&sib_sm[iiN * 128 + dd];
                __nv_bfloat162 m01 = *(__nv_bfloat162*)&wv.x;
                __nv_bfloat162 b01 = *(__nv_bfloat162*)&wv.y;
                __nv_bfloat162 m23 = *(__nv_bfloat162*)&wv.z;
                __nv_bfloat162 b23 = *(__nv_bfloat162*)&wv.w;
                __nv_bfloat162 c01 = __hfma2(sib, b01, m01);
                __nv_bfloat162 c23 = __hfma2(sib, b23, m23);
                uint2 pk;
                pk.x = *(unsigned*)&c01;
                pk.y = *(unsigned*)&c23;
                *(uint2*)(cbuf + dd * 144 + bld_hq * 8) = pk;
            }
        }

        // epilogue: relu + dot W2 into register partials (no shfl/atomics)
        {
            int hb = hc * 64 + wn + (lane & 3) * 2;
            const float2* u2p = (const float2*)(ub_sm + ii * 256);
            const float2* w2p = (const float2*)w2_sm;
            float2 uu[4], ww[4];
#pragma unroll
            for (int n8 = 0; n8 < 4; n8++) {
                uu[n8] = u2p[(hb + n8 * 8) >> 1];
                ww[n8] = w2p[(hb + n8 * 8) >> 1];
            }
#pragma unroll
            for (int mt = 0; mt < 4; mt++) {
                float p0 = sreg[ii][mt][0];
                float p1 = sreg[ii][mt][1];
#pragma unroll
                for (int n8 = 0; n8 < 4; n8++) {
                    const float* A = acc[mt * 4 + n8];
                    p0 = fmaf(fmaxf(A[0] + uu[n8].x, 0.f), ww[n8].x, p0);
                    p0 = fmaf(fmaxf(A[1] + uu[n8].y, 0.f), ww[n8].y, p0);
                    p1 = fmaf(fmaxf(A[2] + uu[n8].x, 0.f), ww[n8].x, p1);
                    p1 = fmaf(fmaxf(A[3] + uu[n8].y, 0.f), ww[n8].y, p1);
                }
                sreg[ii][mt][0] = p0;
                sreg[ii][mt][1] = p1;
            }
        }
        __syncthreads();
    }

    // final reduction: quad-reduce sreg, write per-nwarp parts (alias C, now dead)
    {
        int nw = wn >> 5;   // 0 or 1
#pragma unroll
        for (int ii = 0; ii < 2; ii++)
#pragma unroll
            for (int mt = 0; mt < 4; mt++)
#pragma unroll
                for (int half = 0; half < 2; half++) {
                    float v = sreg[ii][mt][half];
                    v += __shfl_xor_sync(0xffffffffu, v, 1);
                    v += __shfl_xor_sync(0xffffffffu, v, 2);
                    if ((lane & 3) == 0) {
                        int j = wm_ + (lane >> 2) + mt * 16 + half * 8;
                        part_sm[(ii * 2 + nw) * 256 + j] = v;
                    }
                }
    }
    __syncthreads();
    {
        float b2v = bg2[0];
        score_sm[tid]       = part_sm[tid]        + part_sm[256 + tid] + b2v;
        score_sm[256 + tid] = part_sm[512 + tid]  + part_sm[768 + tid] + b2v;
    }
    __syncthreads();

    // ---------------- selection + rescore phase ----------------
    // approx top-12 per row directly on score_sm (destructive)
    if (warp < 2) {
        int r = warp;
        float* scr = score_sm + r * 256;
        for (int t = 0; t < Cv; t++) {
            float bv = -INFINITY; int bidx = Nv;
#pragma unroll
            for (int k = 0; k < 8; k++) {
                int q = k * 32 + lane;
                float v = scr[q];
                if (v > bv || (v == bv && q < bidx)) { bv = v; bidx = q; }
            }
#pragma unroll
            for (int off = 16; off > 0; off >>= 1) {
                float ov = __shfl_down_sync(0xffffffffu, bv, off);
                int   oi = __shfl_down_sync(0xffffffffu, bidx, off);
                if (ov > bv || (ov == bv && oi < bidx)) { bv = ov; bidx = oi; }
            }
            bidx = __shfl_sync(0xffffffffu, bidx, 0);
            if (lane == 0) { sel[r][t] = bidx; scr[bidx] = -INFINITY; }
            __syncwarp();
        }
    }
    __syncthreads();

    // gather candidate s_j rows into selT
#pragma unroll
    for (int k = 0; k < 12; k++) {
        int ii = k * 256 + tid;           // 0..3071
        int d  = ii & 127;
        int rc = ii >> 7;                 // 0..23
        int r  = (rc >= Cv) ? 1 : 0;
        int c  = rc - r * Cv;
        selT[d][rc] = s[(b * Nv + sel[r][c]) * Dv + d];
    }
    __syncthreads();

    // fused exact fp32 rescore (gate + att) for all 24 candidates, FFMA2
    int h = tid;
    unsigned long long ag[2][6], aa[2][6];
#pragma unroll
    for (int r = 0; r < 2; r++)
#pragma unroll
        for (int q = 0; q < 6; q++) { ag[r][q] = 0ull; aa[r][q] = 0ull; }

    const float* pgm = Wg1 + Dv * Hv + h;
    const float* pgb = Wg1 + 2 * Dv * Hv + h;
    const float* pam = Wa1 + Dv * Hv + h;
    const float* pab = Wa1 + 2 * Dv * Hv + h;

#pragma unroll 2
    for (int d = 0; d < Dv; d++) {
        float wgm = pgm[d * Hv];
        float wgb = pgb[d * Hv];
        float wam = pam[d * Hv];
        float wab = pab[d * Hv];
        float s0 = si_sm[d], s1 = si_sm[128 + d];
        float cg0s = fmaf(s0, wgb, wgm);
        float cg1s = fmaf(s1, wgb, wgm);
        float ca0s = fmaf(s0, wab, wam);
        float ca1s = fmaf(s1, wab, wam);
        unsigned long long cg0 = pack2(cg0s, cg0s);
        unsigned long long cg1 = pack2(cg1s, cg1s);
        unsigned long long ca0 = pack2(ca0s, ca0s);
        unsigned long long ca1 = pack2(ca1s, ca1s);

        const ulonglong2* rowp = (const ulonglong2*)&selT[d][0];
#pragma unroll
        for (int q = 0; q < 3; q++) {
            ulonglong2 v0 = rowp[q];
            ffma2(ag[0][q * 2],     v0.x, cg0);
            ffma2(ag[0][q * 2 + 1], v0.y, cg0);
            ffma2(aa[0][q * 2],     v0.x, ca0);
            ffma2(aa[0][q * 2 + 1], v0.y, ca0);
            ulonglong2 v1 = rowp[3 + q];
            ffma2(ag[1][q * 2],     v1.x, cg1);
            ffma2(ag[1][q * 2 + 1], v1.y, cg1);
            ffma2(aa[1][q * 2],     v1.x, ca1);
            ffma2(aa[1][q * 2 + 1], v1.y, ca1);
        }
    }

    // relu + dot W2 for both MLPs, warp reduce, stash partials
#pragma unroll
    for (int r = 0; r < 2; r++) {
        float ug = ub_sm[r * 256 + h];            // includes bg1
        float ua = (r == 0) ? ua0_r : ua1_r;      // includes ba1
        float wg = w2_sm[h];
        float wa = wa2_r;
#pragma unroll
        for (int q = 0; q < 6; q++) {
            float2 g2 = unpack2(ag[r][q]);
            float2 a2 = unpack2(aa[r][q]);
#pragma unroll
            for (int half = 0; half < 2; half++) {
                int t = q * 2 + half;
                float gv = half ? g2.y : g2.x;
                float av = half ? a2.y : a2.x;
                float vg = fmaxf(gv + ug, 0.f) * wg;
                float va = fmaxf(av + ua, 0.f) * wa;
#pragma unroll
                for (int off = 16; off > 0; off >>= 1) {
                    vg += __shfl_xor_sync(0xffffffffu, vg, off);
                    va += __shfl_xor_sync(0xffffffffu, va, off);
                }
                if (lane == 0) {
                    partg[(r * Cv + t) * 8 + warp] = vg;
                    parta[(r * Cv + t) * 8 + warp] = va;
                }
            }
        }
    }
    __syncthreads();

    // block sums
    if (tid < 2 * Cv) {
        int r = tid / Cv, t = tid % Cv;
        float sSum = 0.f;
#pragma unroll
        for (int w8 = 0; w8 < 8; w8++) sSum += partg[(r * Cv + t) * 8 + w8];
        exacts[r][t] = sSum + bg2[0];
    } else if (tid >= 64 && tid < 64 + 2 * Cv) {
        int k = tid - 64;
        int r = k / Cv, t = k % Cv;
        float sSum = 0.f;
#pragma unroll
        for (int w8 = 0; w8 < 8; w8++) sSum += parta[(r * Cv + t) * 8 + w8];
        alog[r][t] = sSum + ba2[0];
    }
    __syncthreads();

    // exact top-8 among 12 candidates (tie -> lowest original j)
    if (warp < 2) {
        int r = warp;
        float v = (lane < Cv) ? exacts[r][lane] : -INFINITY;
        int jj  = (lane < Cv) ? sel[r][lane] : (1 << 30);
        int cc  = lane;
        for (int t = 0; t < Kv; t++) {
            float bv = v; int bj = jj; int bc = cc;
#pragma unroll
            for (int off = 16; off > 0; off >>= 1) {
                float ov = __shfl_down_sync(0xffffffffu, bv, off);
                int   oj = __shfl_down_sync(0xffffffffu, bj, off);
                int   oc = __shfl_down_sync(0xffffffffu, bc, off);
                if (ov > bv || (ov == bv && oj < bj)) { bv = ov; bj = oj; bc = oc; }
            }
            bc = __shfl_sync(0xffffffffu, bc, 0);
            bj = __shfl_sync(0xffffffffu, bj, 0);
            if (lane == 0) { fsel[r][t] = bc; fj[r][t] = bj; }
            if (cc == bc) v = -INFINITY;
        }
    }
    __syncthreads();

    if (tid < 16) {
        int r = tid >> 3, t = tid & 7;
        logit[r][t] = alog[r][fsel[r][t]];
    }
    __syncthreads();
    if (tid < 2) {
        float m = -INFINITY;
#pragma unroll
        for (int t = 0; t < Kv; t++) m = fmaxf(m, logit[tid][t]);
        float e[Kv], ssum = 0.f;
#pragma unroll
        for (int t = 0; t < Kv; t++) { e[t] = expf(logit[tid][t] - m); ssum += e[t]; }
#pragma unroll
        for (int t = 0; t < Kv; t++) attw[tid][t] = e[t] / ssum;
    }
    __syncthreads();

    if (tid < 16) {
        int r = tid >> 3, t = tid & 7;
        int js = fj[r][t];
        gate[(bi0 + r) * Nv + js] = 1.0f;
        att [(bi0 + r) * Nv + js] = attw[r][t];
    }
    if (tid < Dv) {
        int d = tid;
#pragma unroll
        for (int r = 0; r < 2; r++) {
            float cv = 0.f;
#pragma unroll
            for (int t = 0; t < Kv; t++)
                cv = fmaf(attw[r][t], selT[d][r * Cv + fsel[r][t]], cv);
            ctx[(bi0 + r) * Dv + d] = cv;
        }
    }
}

// ---------------------------------------------------------------------------
extern "C" void kernel_launch(void* const* d_in, const int* in_sizes, int n_in,
                              void* d_out, int out_size)
{
    const float* s   = (const float*)d_in[0];
    const float* Wg1 = (const float*)d_in[1];
    const float* bg1 = (const float*)d_in[2];
    const float* Wg2 = (const float*)d_in[3];
    const float* bg2 = (const float*)d_in[4];
    const float* Wa1 = (const float*)d_in[5];
    const float* ba1 = (const float*)d_in[6];
    const float* Wa2 = (const float*)d_in[7];
    const float* ba2 = (const float*)d_in[8];

    float* out  = (float*)d_out;
    float* ctx  = out;
    float* gate = out + Bv * Nv * Dv;
    float* att  = gate + Bv * Nv * Nv;

    cudaFuncSetAttribute(fused_kernel,
                         cudaFuncAttributeMaxDynamicSharedMemorySize, FUS_SMEM);

    prep_kernel<<<ROWS / 4, 256>>>(s, Wg1, bg1, Wa1, ba1, gate, att);
    fused_kernel<<<ROWS / 2, 256, FUS_SMEM>>>(s, Wg1, bg2, Wg2,
                                              Wa1, Wa2, ba2, ctx, gate, att);
}